// round 2
// baseline (speedup 1.0000x reference)
#include <cuda_runtime.h>
#include <math.h>

#define NBATCH 32
#define SEQ    512
#define HID    1024
#define G4     4096
#define NBLK   128   // persistent blocks for the scan (must be <= #SMs)

// ---------------- scratch (device globals: no allocations allowed) ----------
__device__ float g_xz[(size_t)NBATCH * SEQ * G4];   // [B*T, 4H] precomputed x@W + b  (256 MB)
__device__ float g_ht[2][HID * NBATCH];             // h double buffer, transposed [k][b]
__device__ unsigned g_bar_cnt;
__device__ volatile unsigned g_bar_gen;

// ---------------- software grid barrier (128 co-resident blocks) ------------
__device__ __forceinline__ void grid_sync() {
    __syncthreads();
    if (threadIdx.x == 0) {
        __threadfence();
        unsigned gen = g_bar_gen;
        if (atomicAdd(&g_bar_cnt, 1u) == NBLK - 1u) {
            g_bar_cnt = 0u;
            __threadfence();
            g_bar_gen = gen + 1u;
        } else {
            while (g_bar_gen == gen) { }
            __threadfence();
        }
    }
    __syncthreads();
}

// ---------------- kernel A: xz = x @ W + b  (M=16384, N=4096, K=1024) -------
// 128x128 block tile, BK=8, 256 threads, 8x8 per thread (2x2 quadrants of 4x4)
__global__ __launch_bounds__(256, 2) void gemm_xw_kernel(
    const float* __restrict__ x, const float* __restrict__ W,
    const float* __restrict__ bias)
{
    __shared__ float As[8][132];   // [k][m], padded
    __shared__ float Bs[8][128];   // [k][n]

    const int tid = threadIdx.x;
    const int bm = blockIdx.y * 128;
    const int bn = blockIdx.x * 128;
    const int cx = tid & 15;          // col group 0..15
    const int ry = tid >> 4;          // row group 0..15
    const int arow = tid >> 1;        // 0..127
    const int ak4  = (tid & 1) << 2;  // 0 or 4
    const int bkr  = tid >> 5;        // 0..7
    const int bn4  = (tid & 31) << 2; // 0..124

    const float* xp = x + (size_t)(bm + arow) * HID + ak4;
    const float* wp = W + (size_t)bkr * G4 + bn + bn4;

    float acc[2][2][4][4];
    #pragma unroll
    for (int ai = 0; ai < 2; ai++)
        #pragma unroll
        for (int bi = 0; bi < 2; bi++)
            #pragma unroll
            for (int i = 0; i < 4; i++)
                #pragma unroll
                for (int j = 0; j < 4; j++) acc[ai][bi][i][j] = 0.f;

    for (int k0 = 0; k0 < HID; k0 += 8) {
        float4 av = *(const float4*)(xp + k0);
        float4 bv = *(const float4*)(wp + (size_t)k0 * G4);
        As[ak4 + 0][arow] = av.x;
        As[ak4 + 1][arow] = av.y;
        As[ak4 + 2][arow] = av.z;
        As[ak4 + 3][arow] = av.w;
        *(float4*)&Bs[bkr][bn4] = bv;
        __syncthreads();
        #pragma unroll
        for (int kk = 0; kk < 8; kk++) {
            float4 a0 = *(const float4*)&As[kk][ry * 4];
            float4 a1 = *(const float4*)&As[kk][64 + ry * 4];
            float4 b0 = *(const float4*)&Bs[kk][cx * 4];
            float4 b1 = *(const float4*)&Bs[kk][64 + cx * 4];
            float aa[2][4] = {{a0.x, a0.y, a0.z, a0.w}, {a1.x, a1.y, a1.z, a1.w}};
            float bb[2][4] = {{b0.x, b0.y, b0.z, b0.w}, {b1.x, b1.y, b1.z, b1.w}};
            #pragma unroll
            for (int ai = 0; ai < 2; ai++)
                #pragma unroll
                for (int bi = 0; bi < 2; bi++)
                    #pragma unroll
                    for (int i = 0; i < 4; i++)
                        #pragma unroll
                        for (int j = 0; j < 4; j++)
                            acc[ai][bi][i][j] = fmaf(aa[ai][i], bb[bi][j], acc[ai][bi][i][j]);
        }
        __syncthreads();
    }

    #pragma unroll
    for (int bi = 0; bi < 2; bi++) {
        float4 bsv = *(const float4*)(bias + bn + bi * 64 + cx * 4);
        #pragma unroll
        for (int ai = 0; ai < 2; ai++)
            #pragma unroll
            for (int i = 0; i < 4; i++) {
                int row = bm + ai * 64 + ry * 4 + i;
                float4 v;
                v.x = acc[ai][bi][i][0] + bsv.x;
                v.y = acc[ai][bi][i][1] + bsv.y;
                v.z = acc[ai][bi][i][2] + bsv.z;
                v.w = acc[ai][bi][i][3] + bsv.w;
                *(float4*)(g_xz + (size_t)row * G4 + bn + bi * 64 + cx * 4) = v;
            }
    }
}

// ---------------- kernel B: persistent LSTM scan ----------------------------
// grid = 128 blocks x 128 threads. block (bt,kt): batches bt*8..+8, k kt*32..+32.
// thread = (bp,g,tk): 2 batches x 1 gate x 4 k accumulators. c state in regs.
__global__ __launch_bounds__(128) void lstm_scan_kernel(
    const float* __restrict__ x, const float* __restrict__ U,
    float* __restrict__ out)
{
    __shared__ float zs[8][4][32];   // [local_b][gate][k]

    const int tid = threadIdx.x;
    const int bt = blockIdx.x >> 5;      // 0..3  batch split
    const int kt = blockIdx.x & 31;      // 0..31 k tile
    const int bp = tid >> 5;             // warp id 0..3 -> batch pair
    const int gg = (tid >> 3) & 3;       // gate 0..3 (i,f,g,o)
    const int tk = tid & 7;              // 0..7
    const int kloc = tk << 2;            // 0..28
    const int gcol = gg * HID + kt * 32 + kloc;   // column into [0,4H)
    const int lb0 = bp << 1;             // local batch 0,2,4,6
    const int gb0 = (bt << 3) + lb0;     // global batch of pair

    const int clb = tid >> 5;            // gate-phase cell: local batch 0..3 (+4)
    const int ckk = tid & 31;            // gate-phase local k
    const int ckg = kt * 32 + ckk;       // gate-phase global k

    float c0 = 0.f, c1 = 0.f;            // cell state lives in registers

    // zero h buffer 0 (h_0 = 0)
    for (int i = blockIdx.x * 128 + tid; i < HID * NBATCH; i += NBLK * 128)
        g_ht[0][i] = 0.f;
    grid_sync();

    for (int t = 0; t < SEQ; t++) {
        const float* hrd = g_ht[t & 1];
        float* hwr = g_ht[(t + 1) & 1];

        // init accumulators from precomputed xz
        const size_t xz0 = ((size_t)gb0 * SEQ + t) * G4 + gcol;
        float4 z0 = *(const float4*)(g_xz + xz0);
        float4 z1 = *(const float4*)(g_xz + xz0 + (size_t)SEQ * G4);
        float a00 = z0.x, a01 = z0.y, a02 = z0.z, a03 = z0.w;
        float a10 = z1.x, a11 = z1.y, a12 = z1.z, a13 = z1.w;

        const float* Up = U + gcol;
        const float* hp = hrd + gb0;
        #pragma unroll 8
        for (int j = 0; j < HID; j++) {
            const float4 u  = __ldg((const float4*)(Up + (size_t)j * G4));
            const float2 hv = __ldcg((const float2*)(hp + j * NBATCH));  // L2 (coherent)
            a00 = fmaf(u.x, hv.x, a00); a01 = fmaf(u.y, hv.x, a01);
            a02 = fmaf(u.z, hv.x, a02); a03 = fmaf(u.w, hv.x, a03);
            a10 = fmaf(u.x, hv.y, a10); a11 = fmaf(u.y, hv.y, a11);
            a12 = fmaf(u.z, hv.y, a12); a13 = fmaf(u.w, hv.y, a13);
        }
        *(float4*)&zs[lb0][gg][kloc]     = make_float4(a00, a01, a02, a03);
        *(float4*)&zs[lb0 + 1][gg][kloc] = make_float4(a10, a11, a12, a13);
        __syncthreads();

        // gate phase: 256 (b,k) cells over 128 threads -> 2 cells each
        #pragma unroll
        for (int ci = 0; ci < 2; ci++) {
            const int lb = clb + (ci << 2);
            float zi = zs[lb][0][ckk];
            float zf = zs[lb][1][ckk];
            float zc = zs[lb][2][ckk];
            float zo = zs[lb][3][ckk];
            float ig = 1.f / (1.f + __expf(-zi));
            float fg = 1.f / (1.f + __expf(-zf));
            float cg = tanhf(zc);
            float og = 1.f / (1.f + __expf(-zo));
            float cs = ci ? c1 : c0;
            cs = fg * cs + ig * cg;
            if (ci) c1 = cs; else c0 = cs;
            float h = og * tanhf(cs);
            const int b = (bt << 3) + lb;
            hwr[ckg * NBATCH + b] = h;
            const size_t oi = ((size_t)b * SEQ + t) * HID + ckg;
            out[oi] = tanhf(h + __ldg(x + oi));   // residual + tanh epilogue fused
        }
        grid_sync();   // publish h_{t+1} before anyone reads it
    }
}

// ---------------- launch -----------------------------------------------------
extern "C" void kernel_launch(void* const* d_in, const int* in_sizes, int n_in,
                              void* d_out, int out_size) {
    const float* x = (const float*)d_in[0];
    const float* W = (const float*)d_in[1];
    const float* U = (const float*)d_in[2];
    const float* b = (const float*)d_in[3];
    float* out = (float*)d_out;

    dim3 gA(G4 / 128, (NBATCH * SEQ) / 128);   // (32, 128)
    gemm_xw_kernel<<<gA, 256>>>(x, W, b);
    lstm_scan_kernel<<<NBLK, 128>>>(x, U, out);
}

// round 3
// speedup vs baseline: 3.5888x; 3.5888x over previous
#include <cuda_runtime.h>
#include <math.h>

#define NBATCH 32
#define SEQ    512
#define HID    1024
#define G4     4096
#define NBLK   128   // persistent blocks for the scan (must be <= #SMs)

// ---------------- scratch (device globals: no allocations allowed) ----------
__device__ float g_xz[(size_t)NBATCH * SEQ * G4];   // [B, T, 4H] precomputed x@W + b
__device__ float g_ht[2][HID][NBATCH];              // h double buffer, [k][b]
__device__ unsigned g_bar_cnt;
__device__ volatile unsigned g_bar_gen;

// ---------------- software grid barrier (128 co-resident blocks) ------------
__device__ __forceinline__ void grid_sync() {
    __syncthreads();
    if (threadIdx.x == 0) {
        __threadfence();
        unsigned gen = g_bar_gen;
        if (atomicAdd(&g_bar_cnt, 1u) == NBLK - 1u) {
            g_bar_cnt = 0u;
            __threadfence();
            g_bar_gen = gen + 1u;
        } else {
            while (g_bar_gen == gen) { }
            __threadfence();
        }
    }
    __syncthreads();
}

// ---------------- kernel A: xz = x @ W + b  (M=16384, N=4096, K=1024) -------
__global__ __launch_bounds__(256, 2) void gemm_xw_kernel(
    const float* __restrict__ x, const float* __restrict__ W,
    const float* __restrict__ bias)
{
    __shared__ float As[8][132];   // [k][m], padded
    __shared__ float Bs[8][128];   // [k][n]

    const int tid = threadIdx.x;
    const int bm = blockIdx.y * 128;
    const int bn = blockIdx.x * 128;
    const int cx = tid & 15;
    const int ry = tid >> 4;
    const int arow = tid >> 1;
    const int ak4  = (tid & 1) << 2;
    const int bkr  = tid >> 5;
    const int bn4  = (tid & 31) << 2;

    const float* xp = x + (size_t)(bm + arow) * HID + ak4;
    const float* wp = W + (size_t)bkr * G4 + bn + bn4;

    float acc[2][2][4][4];
    #pragma unroll
    for (int ai = 0; ai < 2; ai++)
        #pragma unroll
        for (int bi = 0; bi < 2; bi++)
            #pragma unroll
            for (int i = 0; i < 4; i++)
                #pragma unroll
                for (int j = 0; j < 4; j++) acc[ai][bi][i][j] = 0.f;

    for (int k0 = 0; k0 < HID; k0 += 8) {
        float4 av = *(const float4*)(xp + k0);
        float4 bv = *(const float4*)(wp + (size_t)k0 * G4);
        As[ak4 + 0][arow] = av.x;
        As[ak4 + 1][arow] = av.y;
        As[ak4 + 2][arow] = av.z;
        As[ak4 + 3][arow] = av.w;
        *(float4*)&Bs[bkr][bn4] = bv;
        __syncthreads();
        #pragma unroll
        for (int kk = 0; kk < 8; kk++) {
            float4 a0 = *(const float4*)&As[kk][ry * 4];
            float4 a1 = *(const float4*)&As[kk][64 + ry * 4];
            float4 b0 = *(const float4*)&Bs[kk][cx * 4];
            float4 b1 = *(const float4*)&Bs[kk][64 + cx * 4];
            float aa[2][4] = {{a0.x, a0.y, a0.z, a0.w}, {a1.x, a1.y, a1.z, a1.w}};
            float bb[2][4] = {{b0.x, b0.y, b0.z, b0.w}, {b1.x, b1.y, b1.z, b1.w}};
            #pragma unroll
            for (int ai = 0; ai < 2; ai++)
                #pragma unroll
                for (int bi = 0; bi < 2; bi++)
                    #pragma unroll
                    for (int i = 0; i < 4; i++)
                        #pragma unroll
                        for (int j = 0; j < 4; j++)
                            acc[ai][bi][i][j] = fmaf(aa[ai][i], bb[bi][j], acc[ai][bi][i][j]);
        }
        __syncthreads();
    }

    #pragma unroll
    for (int bi = 0; bi < 2; bi++) {
        float4 bsv = *(const float4*)(bias + bn + bi * 64 + cx * 4);
        #pragma unroll
        for (int ai = 0; ai < 2; ai++)
            #pragma unroll
            for (int i = 0; i < 4; i++) {
                int row = bm + ai * 64 + ry * 4 + i;
                float4 v;
                v.x = acc[ai][bi][i][0] + bsv.x;
                v.y = acc[ai][bi][i][1] + bsv.y;
                v.z = acc[ai][bi][i][2] + bsv.z;
                v.w = acc[ai][bi][i][3] + bsv.w;
                *(float4*)(g_xz + (size_t)row * G4 + bn + bi * 64 + cx * 4) = v;
            }
    }
}

// ---------------- kernel B: persistent LSTM scan ----------------------------
// 128 blocks x 256 threads. block (bt,kt): batches bt*8..+8, k-tile kt*32..+32
// (covering 128 U columns = 4 gates x 32 k). h staged in smem each step.
// MAC phase: 2 warp-halves split the K=1024 reduction; thread = 2 batches x
// 1 gate x 4 cols, 8 FMA per (LDG.128 U + broadcast LDS.64 h).
// Gate phase: 1 cell per thread (8 b x 32 k = 256), c state in 1 register.
__global__ __launch_bounds__(256, 1) void lstm_scan_kernel(
    const float* __restrict__ x, const float* __restrict__ U,
    float* __restrict__ out)
{
    __shared__ float hs[HID][8];          // 32 KB: h slice [k][local_b]
    __shared__ float zs[2][8][4][32];     // 8 KB: partial z [half][lb][gate][k]

    const int tid = threadIdx.x;
    const int bt = blockIdx.x >> 5;       // 0..3 batch group
    const int kt = blockIdx.x & 31;       // 0..31 k tile

    // MAC-phase mapping
    const int wh = tid >> 7;              // k half 0/1
    const int r  = tid & 127;
    const int bp = r >> 5;                // 0..3 batch pair
    const int gg = (r >> 3) & 3;          // gate
    const int tk = r & 7;
    const int kloc = tk << 2;
    const int gcol = gg * HID + kt * 32 + kloc;
    const int lb0 = bp << 1;

    // gate-phase mapping: 1 cell per thread
    const int clb = tid >> 5;             // local batch 0..7
    const int ckk = tid & 31;             // local k 0..31
    const int cgb = (bt << 3) + clb;      // global batch
    const int ckg = kt * 32 + ckk;        // global k

    float cst = 0.f;                      // cell state (register)

    // zero h buffer 0
    for (int i = blockIdx.x * 256 + tid; i < HID * NBATCH; i += NBLK * 256)
        ((float*)g_ht[0])[i] = 0.f;
    grid_sync();

    const float* Ubase = U + gcol + (size_t)(wh * 512) * G4;

    for (int t = 0; t < SEQ; t++) {
        const float (* __restrict__ hrd)[NBATCH] = g_ht[t & 1];
        float (* __restrict__ hwr)[NBATCH] = g_ht[(t + 1) & 1];

        // ---- phase A: load h slice (8 batches x 1024 k) into smem ----
        #pragma unroll
        for (int it = 0; it < 16; it++) {
            int cidx = it * 256 + tid;        // 0..4095 float2 cells
            int j = cidx >> 2;
            int pr = (cidx & 3) << 1;
            float2 v = *(const float2*)&hrd[j][(bt << 3) + pr];
            *(float2*)&hs[j][pr] = v;
        }
        __syncthreads();

        // ---- phase B: z partial = U^T slice @ h over this thread's k half ----
        float a00 = 0.f, a01 = 0.f, a02 = 0.f, a03 = 0.f;
        float a10 = 0.f, a11 = 0.f, a12 = 0.f, a13 = 0.f;
        const float* Up = Ubase;
        const float* hp = &hs[wh * 512][lb0];
        #pragma unroll 4
        for (int j = 0; j < 512; j++) {
            const float4 u  = __ldg((const float4*)(Up + (size_t)j * G4));
            const float2 hv = *(const float2*)(hp + j * 8);
            a00 = fmaf(u.x, hv.x, a00); a01 = fmaf(u.y, hv.x, a01);
            a02 = fmaf(u.z, hv.x, a02); a03 = fmaf(u.w, hv.x, a03);
            a10 = fmaf(u.x, hv.y, a10); a11 = fmaf(u.y, hv.y, a11);
            a12 = fmaf(u.z, hv.y, a12); a13 = fmaf(u.w, hv.y, a13);
        }
        *(float4*)&zs[wh][lb0][gg][kloc]     = make_float4(a00, a01, a02, a03);
        *(float4*)&zs[wh][lb0 + 1][gg][kloc] = make_float4(a10, a11, a12, a13);
        __syncthreads();

        // ---- phase C: gates (1 cell per thread) ----
        {
            const float* xzp = g_xz + ((size_t)cgb * SEQ + t) * G4 + ckg;
            float zi = zs[0][clb][0][ckk] + zs[1][clb][0][ckk] + __ldg(xzp);
            float zf = zs[0][clb][1][ckk] + zs[1][clb][1][ckk] + __ldg(xzp + HID);
            float zc = zs[0][clb][2][ckk] + zs[1][clb][2][ckk] + __ldg(xzp + 2 * HID);
            float zo = zs[0][clb][3][ckk] + zs[1][clb][3][ckk] + __ldg(xzp + 3 * HID);
            float ig = 1.f / (1.f + __expf(-zi));
            float fg = 1.f / (1.f + __expf(-zf));
            float cg = tanhf(zc);
            float og = 1.f / (1.f + __expf(-zo));
            cst = fg * cst + ig * cg;
            float h = og * tanhf(cst);
            hwr[ckg][cgb] = h;
            const size_t oi = ((size_t)cgb * SEQ + t) * HID + ckg;
            out[oi] = tanhf(h + __ldg(x + oi));
        }
        grid_sync();   // publish h_{t+1}
    }
}

// ---------------- launch -----------------------------------------------------
extern "C" void kernel_launch(void* const* d_in, const int* in_sizes, int n_in,
                              void* d_out, int out_size) {
    const float* x = (const float*)d_in[0];
    const float* W = (const float*)d_in[1];
    const float* U = (const float*)d_in[2];
    const float* b = (const float*)d_in[3];
    float* out = (float*)d_out;

    dim3 gA(G4 / 128, (NBATCH * SEQ) / 128);   // (32, 128)
    gemm_xw_kernel<<<gA, 256>>>(x, W, b);
    lstm_scan_kernel<<<NBLK, 256>>>(x, U, out);
}